// round 14
// baseline (speedup 1.0000x reference)
#include <cuda_runtime.h>
#include <cuda_fp16.h>
#include <cstdint>

#define EDIM 64
#define NTH  128

// smem (bytes)
#define QH 0        // Q hi fp16 [128][128], persistent      (32768)
#define QL 32768    // Q lo fp16 [128][128], persistent      (32768)
#define KH 65536    // K hi [128][128]                       (32768)
#define VH 98304    // V hi [128][64]                        (16384)
#define SMEM_BYTES 114688

__device__ __forceinline__ uint32_t smem_u32(const void* p) {
    uint32_t a;
    asm("{ .reg .u64 t; cvta.to.shared.u64 t, %1; cvt.u32.u64 %0, t; }" : "=r"(a) : "l"(p));
    return a;
}
__device__ __forceinline__ float ex2(float x) {
    float r;
    asm("ex2.approx.ftz.f32 %0, %1;" : "=f"(r) : "f"(x));
    return r;
}
__device__ __forceinline__ void ldsm4(uint32_t* r, uint32_t addr) {
    asm volatile("ldmatrix.sync.aligned.m8n8.x4.shared.b16 {%0,%1,%2,%3}, [%4];"
        : "=r"(r[0]), "=r"(r[1]), "=r"(r[2]), "=r"(r[3]) : "r"(addr));
}
__device__ __forceinline__ void ldsm4t(uint32_t* r, uint32_t addr) {
    asm volatile("ldmatrix.sync.aligned.m8n8.x4.trans.shared.b16 {%0,%1,%2,%3}, [%4];"
        : "=r"(r[0]), "=r"(r[1]), "=r"(r[2]), "=r"(r[3]) : "r"(addr));
}
__device__ __forceinline__ void mma16816(float* d, const uint32_t* a, uint32_t b0, uint32_t b1) {
    asm volatile("mma.sync.aligned.m16n8k16.row.col.f32.f16.f16.f32 "
        "{%0,%1,%2,%3}, {%4,%5,%6,%7}, {%8,%9}, {%0,%1,%2,%3};"
        : "+f"(d[0]), "+f"(d[1]), "+f"(d[2]), "+f"(d[3])
        : "r"(a[0]), "r"(a[1]), "r"(a[2]), "r"(a[3]), "r"(b0), "r"(b1));
}

// One 64-j chunk, NT live 16-j tiles, 32 query rows (2 m-tiles) per warp.
template<int NT, bool MASK>
__device__ __forceinline__ void do_chunk(
    uint32_t sb, int jbase,
    int tt, int rr, int cb, int row0 /*=32*wid*/, int mrow,
    float (&o)[2][8][4], float (&mx)[4], float (&l)[4], bool& first)
{
    float s[2][2 * NT][4];
    #pragma unroll
    for (int m = 0; m < 2; ++m)
        #pragma unroll
        for (int nt = 0; nt < 2 * NT; ++nt) { s[m][nt][0]=0.f; s[m][nt][1]=0.f; s[m][nt][2]=0.f; s[m][nt][3]=0.f; }

    const int arow0 = row0 + ((tt & 1) << 3) + rr;          // m=0 A-frag row
    const int arow1 = arow0 + 16;                           // m=1
    const int brow_b = jbase + ((tt >> 1) << 3) + rr;

    #pragma unroll 2
    for (int kc = 0; kc < 8; ++kc) {
        const int ac16 = 2 * kc + (tt >> 1);
        uint32_t a0h[4], a0l[4], a1h[4], a1l[4];
        {
            uint32_t off0 = (uint32_t)(arow0 * 256 + ((ac16 ^ (arow0 & 7)) << 4));
            uint32_t off1 = (uint32_t)(arow1 * 256 + ((ac16 ^ (arow1 & 7)) << 4));
            ldsm4(a0h, sb + QH + off0);
            ldsm4(a0l, sb + QL + off0);
            ldsm4(a1h, sb + QH + off1);
            ldsm4(a1l, sb + QL + off1);
        }
        uint32_t bh[NT][4];
        #pragma unroll
        for (int np = 0; np < NT; ++np) {
            int brow = brow_b + np * 16;
            int bc16 = 2 * kc + (tt & 1);
            uint32_t boff = (uint32_t)(brow * 256 + ((bc16 ^ (brow & 7)) << 4));
            ldsm4(bh[np], sb + KH + boff);
        }
        #pragma unroll
        for (int np = 0; np < NT; ++np) {
            mma16816(s[0][2*np],   a0h, bh[np][0], bh[np][1]);
            mma16816(s[0][2*np+1], a0h, bh[np][2], bh[np][3]);
            mma16816(s[0][2*np],   a0l, bh[np][0], bh[np][1]);
            mma16816(s[0][2*np+1], a0l, bh[np][2], bh[np][3]);
            mma16816(s[1][2*np],   a1h, bh[np][0], bh[np][1]);
            mma16816(s[1][2*np+1], a1h, bh[np][2], bh[np][3]);
            mma16816(s[1][2*np],   a1l, bh[np][0], bh[np][1]);
            mma16816(s[1][2*np+1], a1l, bh[np][2], bh[np][3]);
        }
    }

    // mask + warp-local row max: rows r[m][0]=row0+16m+mrow, r[m][1]=+8
    float rm[4] = {-1e30f, -1e30f, -1e30f, -1e30f};
    #pragma unroll
    for (int m = 0; m < 2; ++m) {
        const int i0 = row0 + 16 * m + mrow;
        const int i1 = i0 + 8;
        #pragma unroll
        for (int nt = 0; nt < 2 * NT; ++nt) {
            if (MASK) {
                int c0 = jbase + nt * 8 + cb;
                #pragma unroll
                for (int cc = 0; cc < 2; ++cc) {
                    float v0 = s[m][nt][cc];
                    float v1 = s[m][nt][2 + cc];
                    if (c0 + cc > i0) v0 = -1e30f;
                    if (c0 + cc > i1) v1 = -1e30f;
                    s[m][nt][cc]     = v0;
                    s[m][nt][2 + cc] = v1;
                    rm[2*m]   = fmaxf(rm[2*m],   v0);
                    rm[2*m+1] = fmaxf(rm[2*m+1], v1);
                }
            } else {
                rm[2*m]   = fmaxf(rm[2*m],   fmaxf(s[m][nt][0], s[m][nt][1]));
                rm[2*m+1] = fmaxf(rm[2*m+1], fmaxf(s[m][nt][2], s[m][nt][3]));
            }
        }
    }
    #pragma unroll
    for (int r = 0; r < 4; ++r) {
        rm[r] = fmaxf(rm[r], __shfl_xor_sync(0xffffffffu, rm[r], 1));
        rm[r] = fmaxf(rm[r], __shfl_xor_sync(0xffffffffu, rm[r], 2));
    }

    if (first) {
        #pragma unroll
        for (int r = 0; r < 4; ++r) mx[r] = rm[r];
        first = false;
    } else {
        float sf[4];
        #pragma unroll
        for (int r = 0; r < 4; ++r) {
            float mn = fmaxf(mx[r], rm[r]);
            sf[r] = ex2(mx[r] - mn);
            mx[r] = mn;
            l[r] *= sf[r];
        }
        #pragma unroll
        for (int m = 0; m < 2; ++m)
            #pragma unroll
            for (int e = 0; e < 8; ++e) {
                o[m][e][0] *= sf[2*m];   o[m][e][1] *= sf[2*m];
                o[m][e][2] *= sf[2*m+1]; o[m][e][3] *= sf[2*m+1];
            }
    }

    // exp2 + pack P (fp16)
    uint32_t ph[2][4 * NT];
    #pragma unroll
    for (int m = 0; m < 2; ++m) {
        #pragma unroll
        for (int nt = 0; nt < 2 * NT; ++nt) {
            float p00 = ex2(s[m][nt][0] - mx[2*m]);
            float p01 = ex2(s[m][nt][1] - mx[2*m]);
            float p10 = ex2(s[m][nt][2] - mx[2*m+1]);
            float p11 = ex2(s[m][nt][3] - mx[2*m+1]);
            l[2*m]   += p00 + p01;
            l[2*m+1] += p10 + p11;
            __half2 h0 = __floats2half2_rn(p00, p01);
            __half2 h1 = __floats2half2_rn(p10, p11);
            ph[m][2*nt]   = *(uint32_t*)&h0;
            ph[m][2*nt+1] = *(uint32_t*)&h1;
        }
    }

    // GEMM2: batch 4 V LDSMs per jc, feed both m-tiles
    #pragma unroll
    for (int jc = 0; jc < NT; ++jc) {
        uint32_t vh[4][4];
        const int vrow = jbase + jc * 16 + ((tt & 1) << 3) + rr;
        #pragma unroll
        for (int ep = 0; ep < 4; ++ep) {
            int vc16 = ep * 2 + (tt >> 1);
            uint32_t voff = (uint32_t)(vrow * 128 + ((vc16 ^ (vrow & 7)) << 4));
            ldsm4t(vh[ep], sb + VH + voff);
        }
        #pragma unroll
        for (int ep = 0; ep < 4; ++ep) {
            mma16816(o[0][2*ep],   ph[0] + 4*jc, vh[ep][0], vh[ep][1]);
            mma16816(o[0][2*ep+1], ph[0] + 4*jc, vh[ep][2], vh[ep][3]);
            mma16816(o[1][2*ep],   ph[1] + 4*jc, vh[ep][0], vh[ep][1]);
            mma16816(o[1][2*ep+1], ph[1] + 4*jc, vh[ep][2], vh[ep][3]);
        }
    }
}

__global__ __launch_bounds__(NTH, 2)
void local_attn_mma(const float* __restrict__ q,  const float* __restrict__ k,
                    const float* __restrict__ qr, const float* __restrict__ kr,
                    const float* __restrict__ v,  float* __restrict__ out, int T)
{
    extern __shared__ char sm[];
    const uint32_t sb = smem_u32(sm);
    const int tid  = threadIdx.x;
    const int wid  = tid >> 5;
    const int lane = tid & 31;
    const int w    = blockIdx.x;
    const int b    = blockIdx.y;

    const long base  = (long)b * T * EDIM;
    const int  qrow0 = w * 128;

    const int nb  = (w == 0) ? 1 : 2;
    const int kb0 = w - nb + 1;

    const float QSCALE = 0.125f * 1.4426950408889634f;

    // ---- phase 0: Q (scaled) -> fp16 hi (QH) + lo residual (QL) ----
    #pragma unroll
    for (int it = 0; it < 32; ++it) {
        int idx = tid + it * NTH;
        int row = idx >> 5, f4 = idx & 31, f = f4 * 4;
        const float* src = (f < 64) ? q : qr;
        float4 val = *(const float4*)(src + base + (long)(qrow0 + row) * EDIM + (f & 63));
        val.x *= QSCALE; val.y *= QSCALE; val.z *= QSCALE; val.w *= QSCALE;
        __half2 h0 = __floats2half2_rn(val.x, val.y);
        __half2 h1 = __floats2half2_rn(val.z, val.w);
        __half2 l0 = __floats2half2_rn(val.x - __half2float(__low2half(h0)),
                                       val.y - __half2float(__high2half(h0)));
        __half2 l1 = __floats2half2_rn(val.z - __half2float(__low2half(h1)),
                                       val.w - __half2float(__high2half(h1)));
        uint32_t off = (uint32_t)(row * 256 + (((f4 >> 1) ^ (row & 7)) << 4) + (f4 & 1) * 8);
        *(uint2*)(sm + QH + off) = make_uint2(*(uint32_t*)&h0, *(uint32_t*)&h1);
        *(uint2*)(sm + QL + off) = make_uint2(*(uint32_t*)&l0, *(uint32_t*)&l1);
    }

    const int mrow = lane >> 2;
    const int cb   = (lane & 3) * 2;
    const int row0 = wid * 32;
    const int rmax = row0 + 31;
    const int tt   = lane >> 3, rr = lane & 7;

    float mx[4] = {-1e30f, -1e30f, -1e30f, -1e30f};
    float l[4]  = {0.f, 0.f, 0.f, 0.f};
    float o[2][8][4];
    #pragma unroll
    for (int m = 0; m < 2; ++m)
        #pragma unroll
        for (int e = 0; e < 8; ++e) { o[m][e][0]=0.f; o[m][e][1]=0.f; o[m][e][2]=0.f; o[m][e][3]=0.f; }

    bool first = true;

    for (int ib = 0; ib < nb; ++ib) {
        const long kbase = base + (long)((kb0 + ib) * 128) * EDIM;

        if (ib > 0) __syncthreads();   // previous block's smem reads complete
        // ---- load+convert K hi and V hi ----
        #pragma unroll
        for (int it = 0; it < 32; ++it) {
            int idx = tid + it * NTH;
            int row = idx >> 5, f4 = idx & 31, f = f4 * 4;
            const float* src = (f < 64) ? k : kr;
            float4 val = *(const float4*)(src + kbase + (long)row * EDIM + (f & 63));
            __half2 h0 = __floats2half2_rn(val.x, val.y);
            __half2 h1 = __floats2half2_rn(val.z, val.w);
            uint32_t off = (uint32_t)(row * 256 + (((f4 >> 1) ^ (row & 7)) << 4) + (f4 & 1) * 8);
            *(uint2*)(sm + KH + off) = make_uint2(*(uint32_t*)&h0, *(uint32_t*)&h1);
        }
        #pragma unroll
        for (int it = 0; it < 16; ++it) {
            int idx = tid + it * NTH;
            int row = idx >> 4, f4 = idx & 15;
            float4 val = *(const float4*)(v + kbase + (long)row * EDIM + f4 * 4);
            __half2 h0 = __floats2half2_rn(val.x, val.y);
            __half2 h1 = __floats2half2_rn(val.z, val.w);
            uint32_t off = (uint32_t)(row * 128 + (((f4 >> 1) ^ (row & 7)) << 4) + (f4 & 1) * 8);
            *(uint2*)(sm + VH + off) = make_uint2(*(uint32_t*)&h0, *(uint32_t*)&h1);
        }
        __syncthreads();

        const bool causal = (ib == nb - 1);

        #pragma unroll 1
        for (int c = 0; c < 2; ++c) {
            const int jbase = c * 64;
            if (!causal) {
                do_chunk<4, false>(sb, jbase, tt, rr, cb, row0, mrow, o, mx, l, first);
            } else {
                if (jbase > rmax) continue;
                const int nt = min(4, ((rmax - jbase) >> 4) + 1);
                const bool msk = (jbase + 16 * nt - 1) > row0;
                switch (nt) {
                    case 1: do_chunk<1, true >(sb, jbase, tt, rr, cb, row0, mrow, o, mx, l, first); break;
                    case 2: do_chunk<2, true >(sb, jbase, tt, rr, cb, row0, mrow, o, mx, l, first); break;
                    case 3: do_chunk<3, true >(sb, jbase, tt, rr, cb, row0, mrow, o, mx, l, first); break;
                    default:
                        if (msk) do_chunk<4, true >(sb, jbase, tt, rr, cb, row0, mrow, o, mx, l, first);
                        else     do_chunk<4, false>(sb, jbase, tt, rr, cb, row0, mrow, o, mx, l, first);
                        break;
                }
            }
        }
    }

    // ---- epilogue: 4 rows per thread ----
    #pragma unroll
    for (int r = 0; r < 4; ++r) {
        l[r] += __shfl_xor_sync(0xffffffffu, l[r], 1);
        l[r] += __shfl_xor_sync(0xffffffffu, l[r], 2);
    }
    #pragma unroll
    for (int m = 0; m < 2; ++m) {
        const int i0 = row0 + 16 * m + mrow;
        float inv0 = 1.0f / l[2*m], inv1 = 1.0f / l[2*m+1];
        float* orow0 = out + base + (long)(qrow0 + i0) * EDIM + cb;
        float* orow1 = orow0 + 8L * EDIM;
        #pragma unroll
        for (int e = 0; e < 8; ++e) {
            *(float2*)(orow0 + e * 8) = make_float2(o[m][e][0] * inv0, o[m][e][1] * inv0);
            *(float2*)(orow1 + e * 8) = make_float2(o[m][e][2] * inv1, o[m][e][3] * inv1);
        }
    }
}

extern "C" void kernel_launch(void* const* d_in, const int* in_sizes, int n_in,
                              void* d_out, int out_size)
{
    const float* q  = (const float*)d_in[0];
    const float* k  = (const float*)d_in[1];
    const float* qr = (const float*)d_in[2];
    const float* kr = (const float*)d_in[3];
    const float* v  = (const float*)d_in[4];
    float* out      = (float*)d_out;

    const int T  = 4096;
    const int Bm = in_sizes[0] / (T * EDIM);
    const int W  = T / 128;

    cudaFuncSetAttribute(local_attn_mma, cudaFuncAttributeMaxDynamicSharedMemorySize, SMEM_BYTES);
    dim3 grid(W, Bm);
    local_attn_mma<<<grid, NTH, SMEM_BYTES>>>(q, k, qr, kr, v, out, T);
}

// round 15
// speedup vs baseline: 1.2069x; 1.2069x over previous
#include <cuda_runtime.h>
#include <cuda_fp16.h>
#include <cstdint>

#define EDIM 64
#define NTH  256

// smem (bytes)
#define QL 0        // Q lo fp16 [128][128], persistent       (32768)
#define KH 32768    // phase 0: Q hi; then K hi [128][128]    (32768)
#define VH 65536    // V hi [128][64]                         (16384)
#define SMEM_BYTES 81920

__device__ __forceinline__ uint32_t smem_u32(const void* p) {
    uint32_t a;
    asm("{ .reg .u64 t; cvta.to.shared.u64 t, %1; cvt.u32.u64 %0, t; }" : "=r"(a) : "l"(p));
    return a;
}
__device__ __forceinline__ float ex2(float x) {
    float r;
    asm("ex2.approx.ftz.f32 %0, %1;" : "=f"(r) : "f"(x));
    return r;
}
__device__ __forceinline__ void ldsm4(uint32_t* r, uint32_t addr) {
    asm volatile("ldmatrix.sync.aligned.m8n8.x4.shared.b16 {%0,%1,%2,%3}, [%4];"
        : "=r"(r[0]), "=r"(r[1]), "=r"(r[2]), "=r"(r[3]) : "r"(addr));
}
__device__ __forceinline__ void ldsm4t(uint32_t* r, uint32_t addr) {
    asm volatile("ldmatrix.sync.aligned.m8n8.x4.trans.shared.b16 {%0,%1,%2,%3}, [%4];"
        : "=r"(r[0]), "=r"(r[1]), "=r"(r[2]), "=r"(r[3]) : "r"(addr));
}
__device__ __forceinline__ void mma16816(float* d, const uint32_t* a, uint32_t b0, uint32_t b1) {
    asm volatile("mma.sync.aligned.m16n8k16.row.col.f32.f16.f16.f32 "
        "{%0,%1,%2,%3}, {%4,%5,%6,%7}, {%8,%9}, {%0,%1,%2,%3};"
        : "+f"(d[0]), "+f"(d[1]), "+f"(d[2]), "+f"(d[3])
        : "r"(a[0]), "r"(a[1]), "r"(a[2]), "r"(a[3]), "r"(b0), "r"(b1));
}
__device__ __forceinline__ uint32_t pack_h2(float a, float b) {
    __half2 h = __floats2half2_rn(a, b);
    return *(uint32_t*)&h;
}

// One 64-j chunk with NT live 16-j tiles, fully static, batched LDSM.
template<int NT, bool MASK>
__device__ __forceinline__ void do_chunk(
    uint32_t sb, int jbase,
    int tt, int rr, int cb, int irow0, int irow1,
    uint32_t abase, int arow,
    const uint32_t (&qf)[8][4],
    float (&o)[8][4], float& mx0, float& mx1, float& l0, float& l1, bool& first)
{
    float s[2 * NT][4];
    #pragma unroll
    for (int nt = 0; nt < 2 * NT; ++nt) { s[nt][0]=0.f; s[nt][1]=0.f; s[nt][2]=0.f; s[nt][3]=0.f; }

    #pragma unroll 2
    for (int kc = 0; kc < 8; ++kc) {
        uint32_t qlf[4];
        {
            int ac16 = 2 * kc + (tt >> 1);
            uint32_t aoff = abase + (uint32_t)((ac16 ^ (arow & 7)) << 4);
            ldsm4(qlf, sb + QL + aoff);
        }
        uint32_t bh[NT][4];
        #pragma unroll
        for (int np = 0; np < NT; ++np) {
            int brow = jbase + np * 16 + ((tt >> 1) << 3) + rr;
            int bc16 = 2 * kc + (tt & 1);
            uint32_t boff = (uint32_t)(brow * 256 + ((bc16 ^ (brow & 7)) << 4));
            ldsm4(bh[np], sb + KH + boff);
        }
        #pragma unroll
        for (int np = 0; np < NT; ++np) {
            mma16816(s[2*np],   qf[kc], bh[np][0], bh[np][1]);
            mma16816(s[2*np+1], qf[kc], bh[np][2], bh[np][3]);
            mma16816(s[2*np],   qlf,    bh[np][0], bh[np][1]);
            mma16816(s[2*np+1], qlf,    bh[np][2], bh[np][3]);
        }
    }

    float rm0 = -1e30f, rm1 = -1e30f;
    #pragma unroll
    for (int nt = 0; nt < 2 * NT; ++nt) {
        if (MASK) {
            int c0 = jbase + nt * 8 + cb;
            #pragma unroll
            for (int cc = 0; cc < 2; ++cc) {
                float v0 = s[nt][cc];
                float v1 = s[nt][2 + cc];
                if (c0 + cc > irow0) v0 = -1e30f;
                if (c0 + cc > irow1) v1 = -1e30f;
                s[nt][cc]     = v0;
                s[nt][2 + cc] = v1;
                rm0 = fmaxf(rm0, v0);
                rm1 = fmaxf(rm1, v1);
            }
        } else {
            rm0 = fmaxf(rm0, fmaxf(s[nt][0], s[nt][1]));
            rm1 = fmaxf(rm1, fmaxf(s[nt][2], s[nt][3]));
        }
    }
    rm0 = fmaxf(rm0, __shfl_xor_sync(0xffffffffu, rm0, 1));
    rm0 = fmaxf(rm0, __shfl_xor_sync(0xffffffffu, rm0, 2));
    rm1 = fmaxf(rm1, __shfl_xor_sync(0xffffffffu, rm1, 1));
    rm1 = fmaxf(rm1, __shfl_xor_sync(0xffffffffu, rm1, 2));

    if (first) {
        mx0 = rm0; mx1 = rm1;
        first = false;
    } else {
        float mn0 = fmaxf(mx0, rm0), mn1 = fmaxf(mx1, rm1);
        float sf0 = ex2(mx0 - mn0), sf1 = ex2(mx1 - mn1);
        mx0 = mn0; mx1 = mn1;
        l0 *= sf0; l1 *= sf1;
        #pragma unroll
        for (int e = 0; e < 8; ++e) {
            o[e][0] *= sf0; o[e][1] *= sf0;
            o[e][2] *= sf1; o[e][3] *= sf1;
        }
    }

    uint32_t ph[4 * NT];
    #pragma unroll
    for (int nt = 0; nt < 2 * NT; ++nt) {
        float p00 = ex2(s[nt][0] - mx0);
        float p01 = ex2(s[nt][1] - mx0);
        float p10 = ex2(s[nt][2] - mx1);
        float p11 = ex2(s[nt][3] - mx1);
        l0 += p00 + p01;
        l1 += p10 + p11;
        ph[2*nt]   = pack_h2(p00, p01);
        ph[2*nt+1] = pack_h2(p10, p11);
    }

    // GEMM2: batch V LDSMs across pairs of jc (8 in flight), then MMAs
    #pragma unroll
    for (int jc0 = 0; jc0 < NT; jc0 += 2) {
        uint32_t vh[2][4][4];
        #pragma unroll
        for (int u = 0; u < 2; ++u) {
            if (jc0 + u >= NT) break;   // static: NT, jc0, u all compile-time
            const int vrow = jbase + (jc0 + u) * 16 + ((tt & 1) << 3) + rr;
            #pragma unroll
            for (int ep = 0; ep < 4; ++ep) {
                int vc16 = ep * 2 + (tt >> 1);
                uint32_t voff = (uint32_t)(vrow * 128 + ((vc16 ^ (vrow & 7)) << 4));
                ldsm4t(vh[u][ep], sb + VH + voff);
            }
        }
        #pragma unroll
        for (int u = 0; u < 2; ++u) {
            if (jc0 + u >= NT) break;
            const uint32_t* Ah = ph + 4 * (jc0 + u);
            #pragma unroll
            for (int ep = 0; ep < 4; ++ep) {
                mma16816(o[2*ep],   Ah, vh[u][ep][0], vh[u][ep][1]);
                mma16816(o[2*ep+1], Ah, vh[u][ep][2], vh[u][ep][3]);
            }
        }
    }
}

__global__ __launch_bounds__(NTH, 2)
void local_attn_mma(const float* __restrict__ q,  const float* __restrict__ k,
                    const float* __restrict__ qr, const float* __restrict__ kr,
                    const float* __restrict__ v,  float* __restrict__ out, int T)
{
    extern __shared__ char sm[];
    const uint32_t sb = smem_u32(sm);
    const int tid  = threadIdx.x;
    const int wid  = tid >> 5;
    const int lane = tid & 31;
    const int w    = blockIdx.x;
    const int b    = blockIdx.y;

    const long base  = (long)b * T * EDIM;
    const int  qrow0 = w * 128;

    const int nb  = (w == 0) ? 1 : 2;
    const int kb0 = w - nb + 1;

    const float QSCALE = 0.125f * 1.4426950408889634f;

    // ---- phase 0: Q (scaled) -> fp16 hi (KH) + lo residual (QL), paired STS.128 ----
    // 2048 f4-pairs; each thread handles 8 pairs; pair p covers f4 = {2p, 2p+1}
    #pragma unroll
    for (int it = 0; it < 8; ++it) {
        int idx = tid + it * NTH;              // 0..2047
        int row = idx >> 4, p = idx & 15;      // 16 pairs per row
        int f = p * 8;                          // first float of the pair
        const float* src = (f < 64) ? q : qr;
        const float* rp = src + base + (long)(qrow0 + row) * EDIM + (f & 63);
        float4 v0 = *(const float4*)(rp);
        float4 v1 = *(const float4*)(rp + 4);
        v0.x *= QSCALE; v0.y *= QSCALE; v0.z *= QSCALE; v0.w *= QSCALE;
        v1.x *= QSCALE; v1.y *= QSCALE; v1.z *= QSCALE; v1.w *= QSCALE;
        uint4 hi, lo;
        hi.x = pack_h2(v0.x, v0.y); hi.y = pack_h2(v0.z, v0.w);
        hi.z = pack_h2(v1.x, v1.y); hi.w = pack_h2(v1.z, v1.w);
        lo.x = pack_h2(v0.x - __half2float(__ushort_as_half((unsigned short)(hi.x & 0xffff))),
                       v0.y - __half2float(__ushort_as_half((unsigned short)(hi.x >> 16))));
        lo.y = pack_h2(v0.z - __half2float(__ushort_as_half((unsigned short)(hi.y & 0xffff))),
                       v0.w - __half2float(__ushort_as_half((unsigned short)(hi.y >> 16))));
        lo.z = pack_h2(v1.x - __half2float(__ushort_as_half((unsigned short)(hi.z & 0xffff))),
                       v1.y - __half2float(__ushort_as_half((unsigned short)(hi.z >> 16))));
        lo.w = pack_h2(v1.z - __half2float(__ushort_as_half((unsigned short)(hi.w & 0xffff))),
                       v1.w - __half2float(__ushort_as_half((unsigned short)(hi.w >> 16))));
        uint32_t off = (uint32_t)(row * 256 + ((p ^ (row & 7)) << 4));
        *(uint4*)(sm + KH + off) = hi;
        *(uint4*)(sm + QL + off) = lo;
    }
    __syncthreads();

    const int mrow  = lane >> 2;
    const int cb    = (lane & 3) * 2;
    const int irow0 = wid * 16 + mrow;
    const int irow1 = irow0 + 8;
    const int rmax  = wid * 16 + 15;
    const int tt    = lane >> 3, rr = lane & 7;
    const int arow  = wid * 16 + ((tt & 1) << 3) + rr;
    const uint32_t abase = (uint32_t)(arow * 256);

    // ---- cache Q-hi A-fragments ----
    uint32_t qf[8][4];
    #pragma unroll
    for (int kc = 0; kc < 8; ++kc) {
        int ac16 = 2 * kc + (tt >> 1);
        uint32_t aoff = abase + (uint32_t)((ac16 ^ (arow & 7)) << 4);
        ldsm4(qf[kc], sb + KH + aoff);
    }
    __syncthreads();

    float mx0 = -1e30f, mx1 = -1e30f, l0 = 0.f, l1 = 0.f;
    float o[8][4];
    #pragma unroll
    for (int e = 0; e < 8; ++e) { o[e][0]=0.f; o[e][1]=0.f; o[e][2]=0.f; o[e][3]=0.f; }

    bool first = true;

    for (int ib = 0; ib < nb; ++ib) {
        const long kbase = base + (long)((kb0 + ib) * 128) * EDIM;

        // ---- load+convert K hi (paired) and V hi (paired) ----
        #pragma unroll
        for (int it = 0; it < 8; ++it) {
            int idx = tid + it * NTH;
            int row = idx >> 4, p = idx & 15;
            int f = p * 8;
            const float* src = (f < 64) ? k : kr;
            const float* rp = src + kbase + (long)row * EDIM + (f & 63);
            float4 v0 = *(const float4*)(rp);
            float4 v1 = *(const float4*)(rp + 4);
            uint4 hi;
            hi.x = pack_h2(v0.x, v0.y); hi.y = pack_h2(v0.z, v0.w);
            hi.z = pack_h2(v1.x, v1.y); hi.w = pack_h2(v1.z, v1.w);
            uint32_t off = (uint32_t)(row * 256 + ((p ^ (row & 7)) << 4));
            *(uint4*)(sm + KH + off) = hi;
        }
        #pragma unroll
        for (int it = 0; it < 4; ++it) {
            int idx = tid + it * NTH;              // 0..1023 pairs
            int row = idx >> 3, p = idx & 7;       // 8 pairs per V row
            const float* rp = v + kbase + (long)row * EDIM + p * 8;
            float4 v0 = *(const float4*)(rp);
            float4 v1 = *(const float4*)(rp + 4);
            uint4 hi;
            hi.x = pack_h2(v0.x, v0.y); hi.y = pack_h2(v0.z, v0.w);
            hi.z = pack_h2(v1.x, v1.y); hi.w = pack_h2(v1.z, v1.w);
            uint32_t off = (uint32_t)(row * 128 + ((p ^ (row & 7)) << 4));
            *(uint4*)(sm + VH + off) = hi;
        }
        __syncthreads();

        const bool causal = (ib == nb - 1);

        #pragma unroll 1
        for (int c = 0; c < 2; ++c) {
            const int jbase = c * 64;
            if (!causal) {
                do_chunk<4, false>(sb, jbase, tt, rr, cb, irow0, irow1, abase, arow,
                                   qf, o, mx0, mx1, l0, l1, first);
            } else {
                if (jbase > rmax) continue;
                const int nt = min(4, ((rmax - jbase) >> 4) + 1);
                const bool msk = (jbase + 16 * nt - 1) > wid * 16;
                switch (nt) {
                    case 1: do_chunk<1, true >(sb, jbase, tt, rr, cb, irow0, irow1, abase, arow, qf, o, mx0, mx1, l0, l1, first); break;
                    case 2: do_chunk<2, true >(sb, jbase, tt, rr, cb, irow0, irow1, abase, arow, qf, o, mx0, mx1, l0, l1, first); break;
                    case 3: do_chunk<3, true >(sb, jbase, tt, rr, cb, irow0, irow1, abase, arow, qf, o, mx0, mx1, l0, l1, first); break;
                    default:
                        if (msk) do_chunk<4, true >(sb, jbase, tt, rr, cb, irow0, irow1, abase, arow, qf, o, mx0, mx1, l0, l1, first);
                        else     do_chunk<4, false>(sb, jbase, tt, rr, cb, irow0, irow1, abase, arow, qf, o, mx0, mx1, l0, l1, first);
                        break;
                }
            }
        }

        if (ib + 1 < nb) __syncthreads();
    }

    // ---- epilogue ----
    l0 += __shfl_xor_sync(0xffffffffu, l0, 1);
    l0 += __shfl_xor_sync(0xffffffffu, l0, 2);
    l1 += __shfl_xor_sync(0xffffffffu, l1, 1);
    l1 += __shfl_xor_sync(0xffffffffu, l1, 2);
    float inv0 = 1.0f / l0, inv1 = 1.0f / l1;
    float* orow0 = out + base + (long)(qrow0 + irow0) * EDIM + cb;
    float* orow1 = out + base + (long)(qrow0 + irow1) * EDIM + cb;
    #pragma unroll
    for (int e = 0; e < 8; ++e) {
        *(float2*)(orow0 + e * 8) = make_float2(o[e][0] * inv0, o[e][1] * inv0);
        *(float2*)(orow1 + e * 8) = make_float2(o[e][2] * inv1, o[e][3] * inv1);
    }
}

extern "C" void kernel_launch(void* const* d_in, const int* in_sizes, int n_in,
                              void* d_out, int out_size)
{
    const float* q  = (const float*)d_in[0];
    const float* k  = (const float*)d_in[1];
    const float* qr = (const float*)d_in[2];
    const float* kr = (const float*)d_in[3];
    const float* v  = (const float*)d_in[4];
    float* out      = (float*)d_out;

    const int T  = 4096;
    const int Bm = in_sizes[0] / (T * EDIM);
    const int W  = T / 128;

    cudaFuncSetAttribute(local_attn_mma, cudaFuncAttributeMaxDynamicSharedMemorySize, SMEM_BYTES);
    dim3 grid(W, Bm);
    local_attn_mma<<<grid, NTH, SMEM_BYTES>>>(q, k, qr, kr, v, out, T);
}

// round 16
// speedup vs baseline: 1.2724x; 1.0542x over previous
#include <cuda_runtime.h>
#include <cuda_fp16.h>
#include <cstdint>

#define EDIM 64
#define NTH  256

// smem (bytes)
#define QL 0        // Q lo fp16 [128][128], persistent       (32768)
#define KH 32768    // phase 0: Q hi; then K hi [128][128]    (32768)
#define VH 65536    // V hi [128][64]                         (16384)
#define SMEM_BYTES 81920

__device__ __forceinline__ uint32_t smem_u32(const void* p) {
    uint32_t a;
    asm("{ .reg .u64 t; cvta.to.shared.u64 t, %1; cvt.u32.u64 %0, t; }" : "=r"(a) : "l"(p));
    return a;
}
__device__ __forceinline__ float ex2(float x) {
    float r;
    asm("ex2.approx.ftz.f32 %0, %1;" : "=f"(r) : "f"(x));
    return r;
}
__device__ __forceinline__ void ldsm4(uint32_t* r, uint32_t addr) {
    asm volatile("ldmatrix.sync.aligned.m8n8.x4.shared.b16 {%0,%1,%2,%3}, [%4];"
        : "=r"(r[0]), "=r"(r[1]), "=r"(r[2]), "=r"(r[3]) : "r"(addr));
}
__device__ __forceinline__ void ldsm4t(uint32_t* r, uint32_t addr) {
    asm volatile("ldmatrix.sync.aligned.m8n8.x4.trans.shared.b16 {%0,%1,%2,%3}, [%4];"
        : "=r"(r[0]), "=r"(r[1]), "=r"(r[2]), "=r"(r[3]) : "r"(addr));
}
__device__ __forceinline__ void mma16816(float* d, const uint32_t* a, uint32_t b0, uint32_t b1) {
    asm volatile("mma.sync.aligned.m16n8k16.row.col.f32.f16.f16.f32 "
        "{%0,%1,%2,%3}, {%4,%5,%6,%7}, {%8,%9}, {%0,%1,%2,%3};"
        : "+f"(d[0]), "+f"(d[1]), "+f"(d[2]), "+f"(d[3])
        : "r"(a[0]), "r"(a[1]), "r"(a[2]), "r"(a[3]), "r"(b0), "r"(b1));
}

// One 64-j chunk with NT live 16-j tiles, fully static, dependency-ordered LDSM.
template<int NT, bool MASK>
__device__ __forceinline__ void do_chunk(
    uint32_t sb, int jbase,
    int tt, int rr, int cb, int irow0, int irow1,
    uint32_t abase, int arow,
    const uint32_t (&qf)[8][4],
    float (&o)[8][4], float& mx0, float& mx1, float& l0, float& l1, bool& first)
{
    float s[2 * NT][4];
    #pragma unroll
    for (int nt = 0; nt < 2 * NT; ++nt) { s[nt][0]=0.f; s[nt][1]=0.f; s[nt][2]=0.f; s[nt][3]=0.f; }

    #pragma unroll 4
    for (int kc = 0; kc < 8; ++kc) {
        // B tiles first (independent of qlf)
        uint32_t bh[NT][4];
        #pragma unroll
        for (int np = 0; np < NT; ++np) {
            int brow = jbase + np * 16 + ((tt >> 1) << 3) + rr;
            int bc16 = 2 * kc + (tt & 1);
            uint32_t boff = (uint32_t)(brow * 256 + ((bc16 ^ (brow & 7)) << 4));
            ldsm4(bh[np], sb + KH + boff);
        }
        // qlf load issues now; its latency hides behind the qf MMAs below
        uint32_t qlf[4];
        {
            int ac16 = 2 * kc + (tt >> 1);
            uint32_t aoff = abase + (uint32_t)((ac16 ^ (arow & 7)) << 4);
            ldsm4(qlf, sb + QL + aoff);
        }
        // qf MMAs (need only bh)
        #pragma unroll
        for (int np = 0; np < NT; ++np) {
            mma16816(s[2*np],   qf[kc], bh[np][0], bh[np][1]);
            mma16816(s[2*np+1], qf[kc], bh[np][2], bh[np][3]);
        }
        // qlf MMAs
        #pragma unroll
        for (int np = 0; np < NT; ++np) {
            mma16816(s[2*np],   qlf, bh[np][0], bh[np][1]);
            mma16816(s[2*np+1], qlf, bh[np][2], bh[np][3]);
        }
    }

    float rm0 = -1e30f, rm1 = -1e30f;
    #pragma unroll
    for (int nt = 0; nt < 2 * NT; ++nt) {
        if (MASK) {
            int c0 = jbase + nt * 8 + cb;
            #pragma unroll
            for (int cc = 0; cc < 2; ++cc) {
                float v0 = s[nt][cc];
                float v1 = s[nt][2 + cc];
                if (c0 + cc > irow0) v0 = -1e30f;
                if (c0 + cc > irow1) v1 = -1e30f;
                s[nt][cc]     = v0;
                s[nt][2 + cc] = v1;
                rm0 = fmaxf(rm0, v0);
                rm1 = fmaxf(rm1, v1);
            }
        } else {
            rm0 = fmaxf(rm0, fmaxf(s[nt][0], s[nt][1]));
            rm1 = fmaxf(rm1, fmaxf(s[nt][2], s[nt][3]));
        }
    }
    rm0 = fmaxf(rm0, __shfl_xor_sync(0xffffffffu, rm0, 1));
    rm0 = fmaxf(rm0, __shfl_xor_sync(0xffffffffu, rm0, 2));
    rm1 = fmaxf(rm1, __shfl_xor_sync(0xffffffffu, rm1, 1));
    rm1 = fmaxf(rm1, __shfl_xor_sync(0xffffffffu, rm1, 2));

    if (first) {
        mx0 = rm0; mx1 = rm1;
        first = false;
    } else {
        float mn0 = fmaxf(mx0, rm0), mn1 = fmaxf(mx1, rm1);
        float sf0 = ex2(mx0 - mn0), sf1 = ex2(mx1 - mn1);
        mx0 = mn0; mx1 = mn1;
        l0 *= sf0; l1 *= sf1;
        #pragma unroll
        for (int e = 0; e < 8; ++e) {
            o[e][0] *= sf0; o[e][1] *= sf0;
            o[e][2] *= sf1; o[e][3] *= sf1;
        }
    }

    uint32_t ph[4 * NT];
    #pragma unroll
    for (int nt = 0; nt < 2 * NT; ++nt) {
        float p00 = ex2(s[nt][0] - mx0);
        float p01 = ex2(s[nt][1] - mx0);
        float p10 = ex2(s[nt][2] - mx1);
        float p11 = ex2(s[nt][3] - mx1);
        l0 += p00 + p01;
        l1 += p10 + p11;
        __half2 h0 = __floats2half2_rn(p00, p01);
        __half2 h1 = __floats2half2_rn(p10, p11);
        ph[2*nt]   = *(uint32_t*)&h0;
        ph[2*nt+1] = *(uint32_t*)&h1;
    }

    // GEMM2: batch the 4 V LDSMs per jc, then 8 MMAs (R13 form)
    #pragma unroll
    for (int jc = 0; jc < NT; ++jc) {
        const uint32_t* Ah = ph + 4 * jc;
        uint32_t vh[4][4];
        #pragma unroll
        for (int ep = 0; ep < 4; ++ep) {
            int vrow = jbase + jc * 16 + ((tt & 1) << 3) + rr;
            int vc16 = ep * 2 + (tt >> 1);
            uint32_t voff = (uint32_t)(vrow * 128 + ((vc16 ^ (vrow & 7)) << 4));
            ldsm4t(vh[ep], sb + VH + voff);
        }
        #pragma unroll
        for (int ep = 0; ep < 4; ++ep) {
            mma16816(o[2*ep],   Ah, vh[ep][0], vh[ep][1]);
            mma16816(o[2*ep+1], Ah, vh[ep][2], vh[ep][3]);
        }
    }
}

__global__ __launch_bounds__(NTH, 2)
void local_attn_mma(const float* __restrict__ q,  const float* __restrict__ k,
                    const float* __restrict__ qr, const float* __restrict__ kr,
                    const float* __restrict__ v,  float* __restrict__ out, int T)
{
    extern __shared__ char sm[];
    const uint32_t sb = smem_u32(sm);
    const int tid  = threadIdx.x;
    const int wid  = tid >> 5;
    const int lane = tid & 31;
    const int w    = blockIdx.x;
    const int b    = blockIdx.y;

    const long base  = (long)b * T * EDIM;
    const int  qrow0 = w * 128;

    const int nb  = (w == 0) ? 1 : 2;
    const int kb0 = w - nb + 1;

    const float QSCALE = 0.125f * 1.4426950408889634f;

    // ---- phase 0: Q (scaled) -> fp16 hi (KH) + lo residual (QL) ----
    #pragma unroll
    for (int it = 0; it < 16; ++it) {
        int idx = tid + it * NTH;
        int row = idx >> 5, f4 = idx & 31, f = f4 * 4;
        const float* src = (f < 64) ? q : qr;
        float4 val = *(const float4*)(src + base + (long)(qrow0 + row) * EDIM + (f & 63));
        val.x *= QSCALE; val.y *= QSCALE; val.z *= QSCALE; val.w *= QSCALE;
        __half2 h0 = __floats2half2_rn(val.x, val.y);
        __half2 h1 = __floats2half2_rn(val.z, val.w);
        __half2 l0 = __floats2half2_rn(val.x - __half2float(__low2half(h0)),
                                       val.y - __half2float(__high2half(h0)));
        __half2 l1 = __floats2half2_rn(val.z - __half2float(__low2half(h1)),
                                       val.w - __half2float(__high2half(h1)));
        uint32_t off = (uint32_t)(row * 256 + (((f4 >> 1) ^ (row & 7)) << 4) + (f4 & 1) * 8);
        *(uint2*)(sm + KH + off) = make_uint2(*(uint32_t*)&h0, *(uint32_t*)&h1);
        *(uint2*)(sm + QL + off) = make_uint2(*(uint32_t*)&l0, *(uint32_t*)&l1);
    }
    __syncthreads();

    const int mrow  = lane >> 2;
    const int cb    = (lane & 3) * 2;
    const int irow0 = wid * 16 + mrow;
    const int irow1 = irow0 + 8;
    const int rmax  = wid * 16 + 15;
    const int tt    = lane >> 3, rr = lane & 7;
    const int arow  = wid * 16 + ((tt & 1) << 3) + rr;
    const uint32_t abase = (uint32_t)(arow * 256);

    // ---- cache Q-hi A-fragments ----
    uint32_t qf[8][4];
    #pragma unroll
    for (int kc = 0; kc < 8; ++kc) {
        int ac16 = 2 * kc + (tt >> 1);
        uint32_t aoff = abase + (uint32_t)((ac16 ^ (arow & 7)) << 4);
        ldsm4(qf[kc], sb + KH + aoff);
    }
    __syncthreads();

    float mx0 = -1e30f, mx1 = -1e30f, l0 = 0.f, l1 = 0.f;
    float o[8][4];
    #pragma unroll
    for (int e = 0; e < 8; ++e) { o[e][0]=0.f; o[e][1]=0.f; o[e][2]=0.f; o[e][3]=0.f; }

    bool first = true;

    for (int ib = 0; ib < nb; ++ib) {
        const long kbase = base + (long)((kb0 + ib) * 128) * EDIM;

        // ---- load+convert K hi and V hi ----
        #pragma unroll
        for (int it = 0; it < 16; ++it) {
            int idx = tid + it * NTH;
            int row = idx >> 5, f4 = idx & 31, f = f4 * 4;
            const float* src = (f < 64) ? k : kr;
            float4 val = *(const float4*)(src + kbase + (long)row * EDIM + (f & 63));
            __half2 h0 = __floats2half2_rn(val.x, val.y);
            __half2 h1 = __floats2half2_rn(val.z, val.w);
            uint32_t off = (uint32_t)(row * 256 + (((f4 >> 1) ^ (row & 7)) << 4) + (f4 & 1) * 8);
            *(uint2*)(sm + KH + off) = make_uint2(*(uint32_t*)&h0, *(uint32_t*)&h1);
        }
        #pragma unroll
        for (int it = 0; it < 8; ++it) {
            int idx = tid + it * NTH;
            int row = idx >> 4, f4 = idx & 15;
            float4 val = *(const float4*)(v + kbase + (long)row * EDIM + f4 * 4);
            __half2 h0 = __floats2half2_rn(val.x, val.y);
            __half2 h1 = __floats2half2_rn(val.z, val.w);
            uint32_t off = (uint32_t)(row * 128 + (((f4 >> 1) ^ (row & 7)) << 4) + (f4 & 1) * 8);
            *(uint2*)(sm + VH + off) = make_uint2(*(uint32_t*)&h0, *(uint32_t*)&h1);
        }
        __syncthreads();

        const bool causal = (ib == nb - 1);

        #pragma unroll 1
        for (int c = 0; c < 2; ++c) {
            const int jbase = c * 64;
            if (!causal) {
                do_chunk<4, false>(sb, jbase, tt, rr, cb, irow0, irow1, abase, arow,
                                   qf, o, mx0, mx1, l0, l1, first);
            } else {
                if (jbase > rmax) continue;
                const int nt = min(4, ((rmax - jbase) >> 4) + 1);
                const bool msk = (jbase + 16 * nt - 1) > wid * 16;
                switch (nt) {
                    case 1: do_chunk<1, true >(sb, jbase, tt, rr, cb, irow0, irow1, abase, arow, qf, o, mx0, mx1, l0, l1, first); break;
                    case 2: do_chunk<2, true >(sb, jbase, tt, rr, cb, irow0, irow1, abase, arow, qf, o, mx0, mx1, l0, l1, first); break;
                    case 3: do_chunk<3, true >(sb, jbase, tt, rr, cb, irow0, irow1, abase, arow, qf, o, mx0, mx1, l0, l1, first); break;
                    default:
                        if (msk) do_chunk<4, true >(sb, jbase, tt, rr, cb, irow0, irow1, abase, arow, qf, o, mx0, mx1, l0, l1, first);
                        else     do_chunk<4, false>(sb, jbase, tt, rr, cb, irow0, irow1, abase, arow, qf, o, mx0, mx1, l0, l1, first);
                        break;
                }
            }
        }

        if (ib + 1 < nb) __syncthreads();
    }

    // ---- epilogue ----
    l0 += __shfl_xor_sync(0xffffffffu, l0, 1);
    l0 += __shfl_xor_sync(0xffffffffu, l0, 2);
    l1 += __shfl_xor_sync(0xffffffffu, l1, 1);
    l1 += __shfl_xor_sync(0xffffffffu, l1, 2);
    float inv0 = 1.0f / l0, inv1 = 1.0f / l1;
    float* orow0 = out + base + (long)(qrow0 + irow0) * EDIM + cb;
    float* orow1 = out + base + (long)(qrow0 + irow1) * EDIM + cb;
    #pragma unroll
    for (int e = 0; e < 8; ++e) {
        *(float2*)(orow0 + e * 8) = make_float2(o[e][0] * inv0, o[e][1] * inv0);
        *(float2*)(orow1 + e * 8) = make_float2(o[e][2] * inv1, o[e][3] * inv1);
    }
}

extern "C" void kernel_launch(void* const* d_in, const int* in_sizes, int n_in,
                              void* d_out, int out_size)
{
    const float* q  = (const float*)d_in[0];
    const float* k  = (const float*)d_in[1];
    const float* qr = (const float*)d_in[2];
    const float* kr = (const float*)d_in[3];
    const float* v  = (const float*)d_in[4];
    float* out      = (float*)d_out;

    const int T  = 4096;
    const int Bm = in_sizes[0] / (T * EDIM);
    const int W  = T / 128;

    cudaFuncSetAttribute(local_attn_mma, cudaFuncAttributeMaxDynamicSharedMemorySize, SMEM_BYTES);
    dim3 grid(W, Bm);
    local_attn_mma<<<grid, NTH, SMEM_BYTES>>>(q, k, qr, kr, v, out, T);
}